// round 3
// baseline (speedup 1.0000x reference)
#include <cuda_runtime.h>
#include <math.h>

#define B_SIZE   8192
#define K_FEATS  32
#define FT_OUT   512
#define BUCKETS  8
#define FT_VOCAB 40960
#define FFT_VOCAB 640

// Scratch: combined table comb[i][f] = ft_w[i][f] + fft_w[i % 640][f]
// 40960 * 512 floats = 83.9 MB (static __device__ array: allowed scratch).
__device__ float g_comb[FT_VOCAB * FT_OUT];

// ---------------------------------------------------------------------------
// Pass 1: build combined table. Fully vectorized float4 streaming.
// Elements: FT_VOCAB * FT_OUT / 4 = 5,242,880 float4s.
// ---------------------------------------------------------------------------
__global__ void combine_kernel(const float4* __restrict__ ftw,
                               const float4* __restrict__ fftw) {
    int i = blockIdx.x * blockDim.x + threadIdx.x;
    if (i >= FT_VOCAB * (FT_OUT / 4)) return;
    int row  = i >> 7;            // FT_OUT/4 = 128 float4 per row
    int c    = i & 127;
    int frow = row % FFT_VOCAB;
    float4 a = ftw[i];
    float4 b = fftw[frow * 128 + c];
    float4 r;
    r.x = a.x + b.x; r.y = a.y + b.y; r.z = a.z + b.z; r.w = a.w + b.w;
    reinterpret_cast<float4*>(g_comb)[i] = r;
}

// ---------------------------------------------------------------------------
// Pass 2: one block per batch row. 128 threads; thread t owns features
// [4t, 4t+4) as float4 accumulators for the stm and nstm halves.
// ---------------------------------------------------------------------------
__global__ __launch_bounds__(128)
void nnue_kernel(const float*  __restrict__ values,
                 const int*    __restrict__ stm_idx,
                 const int*    __restrict__ nstm_idx,
                 const int*    __restrict__ buckets,
                 const float*  __restrict__ ft_b,
                 const float*  __restrict__ fft_b,
                 const float*  __restrict__ out_w,
                 const float*  __restrict__ out_b,
                 float*        __restrict__ out) {
    const int b = blockIdx.x;
    const int t = threadIdx.x;

    __shared__ float vals[K_FEATS];
    __shared__ int   soff[K_FEATS];   // stm row byte-less offsets (elements)
    __shared__ int   noff[K_FEATS];
    __shared__ float red[4];

    if (t < K_FEATS) {
        vals[t] = values[b * K_FEATS + t];
        soff[t] = stm_idx [b * K_FEATS + t] * FT_OUT;
        noff[t] = nstm_idx[b * K_FEATS + t] * FT_OUT;
    }
    __syncthreads();

    float4 acc_s = make_float4(0.f, 0.f, 0.f, 0.f);
    float4 acc_n = make_float4(0.f, 0.f, 0.f, 0.f);

    // Each thread reads float4 at column offset t within each gathered row.
    #pragma unroll
    for (int k = 0; k < K_FEATS; ++k) {
        const float v = vals[k];
        float4 s = *(reinterpret_cast<const float4*>(g_comb + soff[k]) + t);
        float4 n = *(reinterpret_cast<const float4*>(g_comb + noff[k]) + t);
        acc_s.x = fmaf(v, s.x, acc_s.x);
        acc_s.y = fmaf(v, s.y, acc_s.y);
        acc_s.z = fmaf(v, s.z, acc_s.z);
        acc_s.w = fmaf(v, s.w, acc_s.w);
        acc_n.x = fmaf(v, n.x, acc_n.x);
        acc_n.y = fmaf(v, n.y, acc_n.y);
        acc_n.z = fmaf(v, n.z, acc_n.z);
        acc_n.w = fmaf(v, n.w, acc_n.w);
    }

    // bias + clip to [0,1]
    float4 bb = *(reinterpret_cast<const float4*>(ft_b)  + t);
    float4 fb = *(reinterpret_cast<const float4*>(fft_b) + t);
    float h[8];
    h[0] = acc_s.x + bb.x + fb.x;
    h[1] = acc_s.y + bb.y + fb.y;
    h[2] = acc_s.z + bb.z + fb.z;
    h[3] = acc_s.w + bb.w + fb.w;
    h[4] = acc_n.x + bb.x + fb.x;
    h[5] = acc_n.y + bb.y + fb.y;
    h[6] = acc_n.z + bb.z + fb.z;
    h[7] = acc_n.w + bb.w + fb.w;
    #pragma unroll
    for (int i = 0; i < 8; ++i) h[i] = fminf(fmaxf(h[i], 0.f), 1.f);

    // final dot with the selected bucket row of out_w [BUCKETS, 2*FT_OUT]
    const int bk = buckets[b];
    const float* wrow = out_w + bk * (2 * FT_OUT);
    float4 ws = *(reinterpret_cast<const float4*>(wrow)           + t);
    float4 wn = *(reinterpret_cast<const float4*>(wrow + FT_OUT)  + t);

    float local = h[0] * ws.x + h[1] * ws.y + h[2] * ws.z + h[3] * ws.w
                + h[4] * wn.x + h[5] * wn.y + h[6] * wn.z + h[7] * wn.w;

    // block reduce: 4 warps
    #pragma unroll
    for (int o = 16; o > 0; o >>= 1)
        local += __shfl_down_sync(0xffffffffu, local, o);
    if ((t & 31) == 0) red[t >> 5] = local;
    __syncthreads();
    if (t == 0) {
        float s = red[0] + red[1] + red[2] + red[3] + out_b[bk];
        out[b] = 1.0f / (1.0f + expf(-s));
    }
}

extern "C" void kernel_launch(void* const* d_in, const int* in_sizes, int n_in,
                              void* d_out, int out_size) {
    const float* values   = (const float*)d_in[0];
    const int*   stm_idx  = (const int*)  d_in[1];
    const int*   nstm_idx = (const int*)  d_in[2];
    const int*   buckets  = (const int*)  d_in[3];
    const float* ft_w     = (const float*)d_in[4];
    const float* ft_b     = (const float*)d_in[5];
    const float* fft_w    = (const float*)d_in[6];
    const float* fft_b    = (const float*)d_in[7];
    const float* out_w    = (const float*)d_in[8];
    const float* out_b    = (const float*)d_in[9];
    float* out = (float*)d_out;

    (void)in_sizes; (void)n_in; (void)out_size;

    // Pass 1: combined table (ft_w + fft_w[row % 640])
    const int n4 = FT_VOCAB * (FT_OUT / 4);
    combine_kernel<<<(n4 + 255) / 256, 256>>>(
        reinterpret_cast<const float4*>(ft_w),
        reinterpret_cast<const float4*>(fft_w));

    // Pass 2: embedding-bag + bucketed head
    nnue_kernel<<<B_SIZE, 128>>>(values, stm_idx, nstm_idx, buckets,
                                 ft_b, fft_b, out_w, out_b, out);
}

// round 4
// speedup vs baseline: 1.4526x; 1.4526x over previous
#include <cuda_runtime.h>
#include <cuda_fp16.h>
#include <math.h>

#define B_SIZE    8192
#define K_FEATS   32
#define FT_OUT    512
#define BUCKETS   8
#define FT_VOCAB  40960
#define FFT_VOCAB 640

// Combined table in fp16: comb[i][f] = (half)(ft_w[i][f] + fft_w[i % 640][f])
// 40960 * 512 halves = 41.9 MB  (static __device__ scratch: allowed).
// Fits comfortably in L2 -> main-kernel gathers become L2/L1 hits.
__device__ __half g_comb[FT_VOCAB * FT_OUT];

// ---------------------------------------------------------------------------
// Pass 1: build combined fp16 table.
// Each thread handles 8 consecutive floats: 2x float4 loads (ft_w streamed
// with __ldcs so the 84 MB read doesn't evict comb from L2), one 16-byte
// store of 8 halves.
// ---------------------------------------------------------------------------
__global__ void combine_kernel(const float4* __restrict__ ftw,
                               const float4* __restrict__ fftw) {
    int i = blockIdx.x * blockDim.x + threadIdx.x;          // group of 8 floats
    const int ngroups = FT_VOCAB * (FT_OUT / 8);            // 2,621,440
    if (i >= ngroups) return;
    int row  = i >> 6;                                      // 64 groups per row
    int g    = i & 63;
    int frow = row % FFT_VOCAB;

    // two float4s from each table
    float4 a0 = __ldcs(ftw + (size_t)i * 2);
    float4 a1 = __ldcs(ftw + (size_t)i * 2 + 1);
    const float4* fr = fftw + (size_t)frow * (FT_OUT / 4) + g * 2;
    float4 b0 = __ldg(fr);
    float4 b1 = __ldg(fr + 1);

    __half2 h0 = __floats2half2_rn(a0.x + b0.x, a0.y + b0.y);
    __half2 h1 = __floats2half2_rn(a0.z + b0.z, a0.w + b0.w);
    __half2 h2 = __floats2half2_rn(a1.x + b1.x, a1.y + b1.y);
    __half2 h3 = __floats2half2_rn(a1.z + b1.z, a1.w + b1.w);

    uint4 pack;
    pack.x = *reinterpret_cast<unsigned int*>(&h0);
    pack.y = *reinterpret_cast<unsigned int*>(&h1);
    pack.z = *reinterpret_cast<unsigned int*>(&h2);
    pack.w = *reinterpret_cast<unsigned int*>(&h3);
    reinterpret_cast<uint4*>(g_comb)[i] = pack;
}

// ---------------------------------------------------------------------------
// Pass 2: one block per batch row, 128 threads. Thread t owns features
// [4t, 4t+4): per gathered row that's one 8-byte (4 x half) load.
// 128 threads x 8 B = 1 KB = one full fp16 table row, perfectly coalesced.
// ---------------------------------------------------------------------------
__global__ __launch_bounds__(128)
void nnue_kernel(const float*  __restrict__ values,
                 const int*    __restrict__ stm_idx,
                 const int*    __restrict__ nstm_idx,
                 const int*    __restrict__ buckets,
                 const float*  __restrict__ ft_b,
                 const float*  __restrict__ fft_b,
                 const float*  __restrict__ out_w,
                 const float*  __restrict__ out_b,
                 float*        __restrict__ out) {
    const int b = blockIdx.x;
    const int t = threadIdx.x;

    __shared__ float vals[K_FEATS];
    __shared__ int   soff[K_FEATS];   // element offsets into g_comb
    __shared__ int   noff[K_FEATS];
    __shared__ float red[4];

    if (t < K_FEATS) {
        vals[t] = values[b * K_FEATS + t];
        soff[t] = stm_idx [b * K_FEATS + t] * FT_OUT;
        noff[t] = nstm_idx[b * K_FEATS + t] * FT_OUT;
    }
    __syncthreads();

    float4 acc_s = make_float4(0.f, 0.f, 0.f, 0.f);
    float4 acc_n = make_float4(0.f, 0.f, 0.f, 0.f);

    #pragma unroll
    for (int k = 0; k < K_FEATS; ++k) {
        const float v = vals[k];
        uint2 us = *(reinterpret_cast<const uint2*>(g_comb + soff[k]) + t);
        uint2 un = *(reinterpret_cast<const uint2*>(g_comb + noff[k]) + t);

        float2 s0 = __half22float2(*reinterpret_cast<__half2*>(&us.x));
        float2 s1 = __half22float2(*reinterpret_cast<__half2*>(&us.y));
        float2 n0 = __half22float2(*reinterpret_cast<__half2*>(&un.x));
        float2 n1 = __half22float2(*reinterpret_cast<__half2*>(&un.y));

        acc_s.x = fmaf(v, s0.x, acc_s.x);
        acc_s.y = fmaf(v, s0.y, acc_s.y);
        acc_s.z = fmaf(v, s1.x, acc_s.z);
        acc_s.w = fmaf(v, s1.y, acc_s.w);
        acc_n.x = fmaf(v, n0.x, acc_n.x);
        acc_n.y = fmaf(v, n0.y, acc_n.y);
        acc_n.z = fmaf(v, n1.x, acc_n.z);
        acc_n.w = fmaf(v, n1.y, acc_n.w);
    }

    // bias + clip to [0,1] (biases kept in fp32 for exactness)
    float4 bb = *(reinterpret_cast<const float4*>(ft_b)  + t);
    float4 fb = *(reinterpret_cast<const float4*>(fft_b) + t);
    float h[8];
    h[0] = acc_s.x + bb.x + fb.x;
    h[1] = acc_s.y + bb.y + fb.y;
    h[2] = acc_s.z + bb.z + fb.z;
    h[3] = acc_s.w + bb.w + fb.w;
    h[4] = acc_n.x + bb.x + fb.x;
    h[5] = acc_n.y + bb.y + fb.y;
    h[6] = acc_n.z + bb.z + fb.z;
    h[7] = acc_n.w + bb.w + fb.w;
    #pragma unroll
    for (int i = 0; i < 8; ++i) h[i] = fminf(fmaxf(h[i], 0.f), 1.f);

    // final dot with the selected bucket row of out_w [BUCKETS, 2*FT_OUT]
    const int bk = buckets[b];
    const float* wrow = out_w + bk * (2 * FT_OUT);
    float4 ws = *(reinterpret_cast<const float4*>(wrow)          + t);
    float4 wn = *(reinterpret_cast<const float4*>(wrow + FT_OUT) + t);

    float local = h[0] * ws.x + h[1] * ws.y + h[2] * ws.z + h[3] * ws.w
                + h[4] * wn.x + h[5] * wn.y + h[6] * wn.z + h[7] * wn.w;

    #pragma unroll
    for (int o = 16; o > 0; o >>= 1)
        local += __shfl_down_sync(0xffffffffu, local, o);
    if ((t & 31) == 0) red[t >> 5] = local;
    __syncthreads();
    if (t == 0) {
        float s = red[0] + red[1] + red[2] + red[3] + out_b[bk];
        out[b] = 1.0f / (1.0f + expf(-s));
    }
}

extern "C" void kernel_launch(void* const* d_in, const int* in_sizes, int n_in,
                              void* d_out, int out_size) {
    const float* values   = (const float*)d_in[0];
    const int*   stm_idx  = (const int*)  d_in[1];
    const int*   nstm_idx = (const int*)  d_in[2];
    const int*   buckets  = (const int*)  d_in[3];
    const float* ft_w     = (const float*)d_in[4];
    const float* ft_b     = (const float*)d_in[5];
    const float* fft_w    = (const float*)d_in[6];
    const float* fft_b    = (const float*)d_in[7];
    const float* out_w    = (const float*)d_in[8];
    const float* out_b    = (const float*)d_in[9];
    float* out = (float*)d_out;

    (void)in_sizes; (void)n_in; (void)out_size;

    // Pass 1: combined fp16 table (ft_w + fft_w[row % 640])
    const int ngroups = FT_VOCAB * (FT_OUT / 8);
    combine_kernel<<<(ngroups + 255) / 256, 256>>>(
        reinterpret_cast<const float4*>(ft_w),
        reinterpret_cast<const float4*>(fft_w));

    // Pass 2: embedding-bag + bucketed head
    nnue_kernel<<<B_SIZE, 128>>>(values, stm_idx, nstm_idx, buckets,
                                 ft_b, fft_b, out_w, out_b, out);
}

// round 5
// speedup vs baseline: 1.6659x; 1.1468x over previous
#include <cuda_runtime.h>
#include <cuda_fp16.h>
#include <math.h>

#define B_SIZE    8192
#define K_FEATS   32
#define FT_OUT    512
#define BUCKETS   8
#define FT_VOCAB  40960
#define FFT_VOCAB 640

// Combined table in fp16: comb[i][f] = (half)(ft_w[i][f] + fft_w[i % 640][f])
// 40960 * 512 halves = 41.9 MB (static __device__ scratch).
__device__ __half g_comb[FT_VOCAB * FT_OUT];

// ---------------------------------------------------------------------------
// Pass 1: build combined fp16 table (unchanged from R3; ~DRAM-bound).
// ---------------------------------------------------------------------------
__global__ void combine_kernel(const float4* __restrict__ ftw,
                               const float4* __restrict__ fftw) {
    int i = blockIdx.x * blockDim.x + threadIdx.x;          // group of 8 floats
    const int ngroups = FT_VOCAB * (FT_OUT / 8);
    if (i >= ngroups) return;
    int row  = i >> 6;                                      // 64 groups per row
    int g    = i & 63;
    int frow = row % FFT_VOCAB;

    float4 a0 = __ldcs(ftw + (size_t)i * 2);
    float4 a1 = __ldcs(ftw + (size_t)i * 2 + 1);
    const float4* fr = fftw + (size_t)frow * (FT_OUT / 4) + g * 2;
    float4 b0 = __ldg(fr);
    float4 b1 = __ldg(fr + 1);

    __half2 h0 = __floats2half2_rn(a0.x + b0.x, a0.y + b0.y);
    __half2 h1 = __floats2half2_rn(a0.z + b0.z, a0.w + b0.w);
    __half2 h2 = __floats2half2_rn(a1.x + b1.x, a1.y + b1.y);
    __half2 h3 = __floats2half2_rn(a1.z + b1.z, a1.w + b1.w);

    uint4 pack;
    pack.x = *reinterpret_cast<unsigned int*>(&h0);
    pack.y = *reinterpret_cast<unsigned int*>(&h1);
    pack.z = *reinterpret_cast<unsigned int*>(&h2);
    pack.w = *reinterpret_cast<unsigned int*>(&h3);
    reinterpret_cast<uint4*>(g_comb)[i] = pack;
}

// ---------------------------------------------------------------------------
// Pass 2: one block per batch row, 128 threads.
//   warps 0-1 (t < 64):  stm half,  thread owns features [8*t,   8*t+8)
//   warps 2-3 (t >= 64): nstm half, thread owns features [8*(t-64), ...)
// Hot loop per k: one LDG.128 (8 halves) + 4 HFMA2. Accumulation in half2,
// split into 4 sets of 8 terms to bound fp16 rounding, merged in fp32.
// ---------------------------------------------------------------------------
__global__ __launch_bounds__(128)
void nnue_kernel(const float*  __restrict__ values,
                 const int*    __restrict__ stm_idx,
                 const int*    __restrict__ nstm_idx,
                 const int*    __restrict__ buckets,
                 const float*  __restrict__ ft_b,
                 const float*  __restrict__ fft_b,
                 const float*  __restrict__ out_w,
                 const float*  __restrict__ out_b,
                 float*        __restrict__ out) {
    const int b = blockIdx.x;
    const int t = threadIdx.x;
    const int half_sel = t >> 6;       // 0 = stm, 1 = nstm
    const int col      = t & 63;       // feature group within the half

    __shared__ __half2 vals2[K_FEATS];
    __shared__ int     off2[2 * K_FEATS];   // [0,32): stm offs, [32,64): nstm
    __shared__ float   red[4];

    if (t < K_FEATS) {
        vals2[t] = __float2half2_rn(values[b * K_FEATS + t]);
        off2[t]            = stm_idx [b * K_FEATS + t] * FT_OUT;
        off2[K_FEATS + t]  = nstm_idx[b * K_FEATS + t] * FT_OUT;
    }
    __syncthreads();

    const int* offp = off2 + half_sel * K_FEATS;

    // 4 sets x 4 half2 accumulators (each set takes 8 of the 32 terms)
    __half2 acc[4][4];
    #pragma unroll
    for (int s = 0; s < 4; ++s)
        #pragma unroll
        for (int p = 0; p < 4; ++p)
            acc[s][p] = __float2half2_rn(0.f);

    #pragma unroll
    for (int k = 0; k < K_FEATS; ++k) {
        const __half2 v2 = vals2[k];
        uint4 w = *reinterpret_cast<const uint4*>(g_comb + offp[k] + col * 8);
        const __half2* wp = reinterpret_cast<const __half2*>(&w);
        const int s = k >> 3;          // compile-time under full unroll
        acc[s][0] = __hfma2(v2, wp[0], acc[s][0]);
        acc[s][1] = __hfma2(v2, wp[1], acc[s][1]);
        acc[s][2] = __hfma2(v2, wp[2], acc[s][2]);
        acc[s][3] = __hfma2(v2, wp[3], acc[s][3]);
    }

    // Merge accumulator sets in fp32
    float h[8];
    #pragma unroll
    for (int p = 0; p < 4; ++p) {
        float2 f = make_float2(0.f, 0.f);
        #pragma unroll
        for (int s = 0; s < 4; ++s) {
            float2 a = __half22float2(acc[s][p]);
            f.x += a.x; f.y += a.y;
        }
        h[2 * p]     = f.x;
        h[2 * p + 1] = f.y;
    }

    // bias (fp32) + clip to [0,1]; same biases for both halves
    const float4* bb = reinterpret_cast<const float4*>(ft_b)  + col * 2;
    const float4* fb = reinterpret_cast<const float4*>(fft_b) + col * 2;
    float4 b0 = bb[0], b1 = bb[1], f0 = fb[0], f1 = fb[1];
    h[0] += b0.x + f0.x;  h[1] += b0.y + f0.y;
    h[2] += b0.z + f0.z;  h[3] += b0.w + f0.w;
    h[4] += b1.x + f1.x;  h[5] += b1.y + f1.y;
    h[6] += b1.z + f1.z;  h[7] += b1.w + f1.w;
    #pragma unroll
    for (int i = 0; i < 8; ++i) h[i] = fminf(fmaxf(h[i], 0.f), 1.f);

    // dot with the selected bucket row of out_w [BUCKETS, 2*FT_OUT]
    const int bk = buckets[b];
    const float4* wrow = reinterpret_cast<const float4*>(
        out_w + bk * (2 * FT_OUT) + half_sel * FT_OUT) + col * 2;
    float4 w0 = wrow[0], w1 = wrow[1];

    float local = h[0] * w0.x + h[1] * w0.y + h[2] * w0.z + h[3] * w0.w
                + h[4] * w1.x + h[5] * w1.y + h[6] * w1.z + h[7] * w1.w;

    #pragma unroll
    for (int o = 16; o > 0; o >>= 1)
        local += __shfl_down_sync(0xffffffffu, local, o);
    if ((t & 31) == 0) red[t >> 5] = local;
    __syncthreads();
    if (t == 0) {
        float s = red[0] + red[1] + red[2] + red[3] + out_b[bk];
        out[b] = 1.0f / (1.0f + expf(-s));
    }
}

extern "C" void kernel_launch(void* const* d_in, const int* in_sizes, int n_in,
                              void* d_out, int out_size) {
    const float* values   = (const float*)d_in[0];
    const int*   stm_idx  = (const int*)  d_in[1];
    const int*   nstm_idx = (const int*)  d_in[2];
    const int*   buckets  = (const int*)  d_in[3];
    const float* ft_w     = (const float*)d_in[4];
    const float* ft_b     = (const float*)d_in[5];
    const float* fft_w    = (const float*)d_in[6];
    const float* fft_b    = (const float*)d_in[7];
    const float* out_w    = (const float*)d_in[8];
    const float* out_b    = (const float*)d_in[9];
    float* out = (float*)d_out;

    (void)in_sizes; (void)n_in; (void)out_size;

    const int ngroups = FT_VOCAB * (FT_OUT / 8);
    combine_kernel<<<(ngroups + 255) / 256, 256>>>(
        reinterpret_cast<const float4*>(ft_w),
        reinterpret_cast<const float4*>(fft_w));

    nnue_kernel<<<B_SIZE, 128>>>(values, stm_idx, nstm_idx, buckets,
                                 ft_b, fft_b, out_w, out_b, out);
}